// round 12
// baseline (speedup 1.0000x reference)
#include <cuda_runtime.h>
#include <cuda_bf16.h>
#include <math.h>

// ---------------------------------------------------------------------------
// Soft-VM single step. eq_gate/silu_threshold with SCALE=20 underflow to exact
// fp32 zero beyond |diff| ~ 5.7, so all soft reads/writes over the 16M-entry
// memory are supported on +/-8 windows. Bulk work = the 128 MB memory copy.
// Proven best shape (R6/R10): 296 blocks, 2/SM, contiguous granule-aligned
// chunks, unguarded batches, evict-first source loads. This round isolates
// ONE variable: MLP 4 -> 8 inside that exact layout.
// ---------------------------------------------------------------------------

#define SCALE_F 20.0f

__device__ __forceinline__ float silu_f(float x) {
    return __fdividef(x, 1.0f + __expf(-x));
}

__device__ __forceinline__ float silu_th(float x) {
    float d = SCALE_F * x;
    return (silu_f(d + 0.5f * SCALE_F) - silu_f(d - 0.5f * SCALE_F)) * (1.0f / SCALE_F);
}

__device__ __forceinline__ float sw_mul(float a, float b) {
    return a * silu_f(b) - a * silu_f(-b);
}

__device__ __forceinline__ float eq_g(float a, float b) {
    float diff = a - b;
    return silu_th(diff + 0.5f) * silu_th(-diff + 0.5f);
}

__device__ __forceinline__ float ge_g(float a, float b) {
    return silu_th(a - b + 0.5f);
}

__device__ __forceinline__ float gt_g(float a, float b) {
    return silu_th(a - b - 0.5f);
}

__device__ __forceinline__ float pulse_f(float x, float c) {
    float d = x - c;
    return sw_mul(silu_th(d + 0.5f), silu_th(-d + 0.5f));
}

__device__ __forceinline__ float warp_sum(float v) {
    #pragma unroll
    for (int o = 16; o > 0; o >>= 1) v += __shfl_down_sync(0xffffffffu, v, o);
    return v;
}

// Opcodes
#define OP_LEA 0
#define OP_IMM 1
#define OP_JMP 2
#define OP_JSR 3
#define OP_BZ  4
#define OP_BNZ 5
#define OP_ENT 6
#define OP_ADJ 7
#define OP_LEV 8
#define OP_LI  9
#define OP_LC  10
#define OP_SI  11
#define OP_SC  12
#define OP_PSH 13
#define OP_SHL 23
#define OP_SHR 24
#define OP_ADD 25
#define OP_SUB 26
#define OP_MUL 27
#define OP_DIV 28
#define OP_MOD 29

// Step -> patch handoff (written by block 0, read by the last block).
__device__ int   d_patch_lo[5];        // window low position per write window
__device__ float d_patch_val[5 * 17];  // composed final values per window slot
__device__ int   d_done = 0;           // last-block counter (self-resetting)

#define CPY_THREADS 512
#define CPY_V       8                       // float4 per thread per batch (MLP=8)
#define GRAN        (CPY_THREADS * CPY_V)   // 4096 float4 = 64 KB granule
#define NUM_BLOCKS  296   // 148 SMs x 2 blocks; block 0 = step, 1..295 = copy
#define NUM_COPY    (NUM_BLOCKS - 1)

// ---------------------------------------------------------------------------
// The step computation (runs entirely inside block 0 of the fused kernel).
// ---------------------------------------------------------------------------
__device__ void step_body(const float* __restrict__ mem,
                          const float* __restrict__ pcp,
                          const float* __restrict__ spp,
                          const float* __restrict__ bpp,
                          const float* __restrict__ axp,
                          float* __restrict__ out, int memn) {
    __shared__ float s_reads[5];   // [inst, stack_top, mem[ax], bp_from_stack, pc_from_stack]
    __shared__ float s_divp[8];
    __shared__ float s_shl_sum, s_shr_sum;
    __shared__ float s_g[30];      // opcode gates
    __shared__ float s_cmp[8];     // extra gates
    __shared__ float s_wa[5], s_wv[5];
    __shared__ float s_pg[5][85];  // patch gates: [write i][window j * 17 + k]

    int tid = threadIdx.x;
    float pc = __ldg(pcp), sp = __ldg(spp), bp = __ldg(bpp), ax = __ldg(axp);

    // ---- Phase 1: 5 windowed soft reads, one warp each, lane-parallel ----
    if (tid < 160) {
        int j = tid >> 5, k = tid & 31;
        float addr = (j == 0) ? pc
                   : (j == 1) ? sp
                   : (j == 2) ? ax
                   : (j == 3) ? bp
                   : (sp + 8.0f);
        float w = 0.0f, wm = 0.0f;
        if (k < 17) {
            float cl = fminf(fmaxf(addr, -64.0f), (float)memn + 64.0f);
            long long p = (long long)llrintf(cl) - 8 + k;
            if (p >= 0 && p < (long long)memn) {
                w  = eq_g(addr, (float)p);
                wm = w * __ldg(&mem[p]);
            }
        }
        w  = warp_sum(w);
        wm = warp_sum(wm);
        if (k == 0) s_reads[j] = wm / (w + 1e-8f);
    }
    __syncthreads();

    float stack_top = s_reads[1];
    float instruction = s_reads[0];
    float imm    = floorf(instruction / 256.0f);
    float opcode = instruction - imm * 256.0f;   // jnp.remainder(inst, 256)
    float ax_safe = ax + eq_g(ax, 0.0f);

    // ---- Phase 2 (parallel): div terms, opcode gates, cmp gates, shifts ----
    if (tid < 256) {
        float q = (float)tid;
        float a = stack_top, b = ax_safe;
        float t1 = a - q * b + 0.5f;
        float th1 = (silu_f(SCALE_F * (t1 + 0.5f)) - silu_f(SCALE_F * (t1 - 0.5f))) * (1.0f / SCALE_F);
        float t2 = a - (q + 1.0f) * b + 0.5f;
        float th2 = (silu_f(SCALE_F * (t2 + 0.5f)) - silu_f(SCALE_F * (t2 - 0.5f))) * (1.0f / SCALE_F);
        float term = warp_sum((th1 - th2) * q);
        if ((tid & 31) == 0) s_divp[tid >> 5] = term;
    } else if (tid < 286) {
        int op = tid - 256;
        s_g[op] = eq_g(opcode, (float)op);
    } else if (tid >= 288 && tid < 320) {
        int l = tid - 288;
        float r = 0.0f;
        if (l == 0) r = eq_g(ax, 0.0f);
        else if (l == 1) r = eq_g(stack_top, ax);
        else if (l == 2) r = gt_g(ax, stack_top);
        else if (l == 3) r = gt_g(stack_top, ax);
        else if (l == 4) r = ge_g(ax, stack_top);
        else if (l == 5) r = ge_g(stack_top, ax);
        else if (l == 6) r = sw_mul(stack_top, ax);
        if (l < 7) s_cmp[l] = r;
    } else if (tid >= 320 && tid < 352) {
        int i = tid - 320;
        float fi = (float)i;
        float p2 = exp2f(fi);
        float pul = pulse_f(ax, fi);
        float shl = sw_mul(stack_top, p2) * pul;
        float shr = floorf(__fdividef(stack_top, p2)) * pul;
        shl = warp_sum(shl);
        shr = warp_sum(shr);
        if (i == 0) { s_shl_sum = shl; s_shr_sum = shr; }
    }
    __syncthreads();

    // ---- Phase 3: thread 0 cheap scalar combine ----
    if (tid == 0) {
        float div_result = 0.0f;
        #pragma unroll
        for (int i = 0; i < 8; i++) div_result += s_divp[i];
        float shl_result = s_shl_sum, shr_result = s_shr_sum;

        float li_result     = s_reads[2];
        float bp_from_stack = s_reads[3];
        float pc_from_stack = s_reads[4];
        float pc_next = pc + 8.0f;

        float eq_ax0    = s_cmp[0];
        float eq_st_ax  = s_cmp[1];
        float mul_st_ax = s_cmp[6];

        float add_r = stack_top + ax;
        float sub_r = stack_top - ax;
        float mul_r = mul_st_ax;
        float mod_r = stack_top - sw_mul(div_result, ax_safe);
        float or_r  = stack_top + ax - mul_st_ax;
        float xor_r = stack_top + ax - 2.0f * mul_st_ax;
        float and_r = mul_st_ax;
        float eq_r  = eq_st_ax;
        float ne_r  = 1.0f - eq_st_ax;
        float lt_r  = s_cmp[2];
        float gt_r  = s_cmp[3];
        float le_r  = s_cmp[4];
        float ge_r  = s_cmp[5];
        float lea_r = bp + imm;

        float gate_sum = s_g[OP_LEA] + s_g[OP_IMM] + s_g[OP_LI] + s_g[OP_LC]
                       + s_g[OP_ADD] + s_g[OP_SUB] + s_g[OP_MUL] + s_g[OP_DIV]
                       + s_g[OP_MOD] + s_g[OP_SHL] + s_g[OP_SHR] + s_g[14]
                       + s_g[15] + s_g[16] + s_g[17] + s_g[18] + s_g[19]
                       + s_g[20] + s_g[21] + s_g[22];

        float new_ax = ax * (1.0f - gate_sum)
                     + lea_r * s_g[OP_LEA] + imm * s_g[OP_IMM]
                     + li_result * s_g[OP_LI] + li_result * s_g[OP_LC]
                     + add_r * s_g[OP_ADD] + sub_r * s_g[OP_SUB] + mul_r * s_g[OP_MUL]
                     + div_result * s_g[OP_DIV] + mod_r * s_g[OP_MOD]
                     + shl_result * s_g[OP_SHL] + shr_result * s_g[OP_SHR]
                     + or_r * s_g[14] + xor_r * s_g[15] + and_r * s_g[16]
                     + eq_r * s_g[17] + ne_r * s_g[18] + lt_r * s_g[19]
                     + gt_r * s_g[20] + le_r * s_g[21] + ge_r * s_g[22];

        float g_psh = s_g[OP_PSH], g_adj = s_g[OP_ADJ];
        float g_ent = s_g[OP_ENT], g_lev = s_g[OP_LEV];

        float pops = s_g[OP_ADD] + s_g[OP_SUB] + s_g[OP_MUL] + s_g[OP_DIV]
                   + s_g[OP_MOD] + s_g[OP_SHL] + s_g[OP_SHR] + s_g[14] + s_g[15]
                   + s_g[16] + s_g[17] + s_g[18] + s_g[19] + s_g[20] + s_g[21]
                   + s_g[22];

        float new_sp = sp * (1.0f - g_psh - g_adj - g_ent - g_lev - pops)
                     + (sp - 8.0f) * g_psh + (sp + imm) * g_adj + (sp - imm) * g_ent
                     + bp * g_lev + (sp + 8.0f) * pops;

        float new_bp = bp * (1.0f - g_ent - g_lev) + sp * g_ent + bp_from_stack * g_lev;

        float g_jmp = s_g[OP_JMP], g_jsr = s_g[OP_JSR];
        float bz_take  = sw_mul(s_g[OP_BZ], eq_ax0);
        float bnz_take = sw_mul(s_g[OP_BNZ], 1.0f - eq_ax0);

        float new_pc = pc_next * (1.0f - g_jmp - g_jsr - bz_take - bnz_take - g_lev)
                     + imm * g_jmp + imm * g_jsr + imm * bz_take + imm * bnz_take
                     + pc_from_stack * g_lev;

        out[0] = rintf(new_pc);   // jnp.round == half-to-even == rintf
        out[1] = rintf(new_sp);
        out[2] = rintf(new_bp);
        out[3] = rintf(new_ax);

        // The 5 sequential soft writes (order matters; composed below)
        s_wa[0] = (sp - 8.0f) * g_psh;      s_wv[0] = ax * g_psh;
        s_wa[1] = (sp - 8.0f) * g_jsr;      s_wv[1] = pc_next * g_jsr;
        s_wa[2] = (sp - 8.0f) * g_ent;      s_wv[2] = bp * g_ent;
        s_wa[3] = stack_top * s_g[OP_SI];   s_wv[3] = ax * s_g[OP_SI];
        s_wa[4] = stack_top * s_g[OP_SC];   s_wv[4] = ax * s_g[OP_SC];
    }
    __syncthreads();

    // ---- Phase 4a: all 5x5x17 patch gates in parallel ----
    if (tid < 425) {
        int w = tid / 85;          // which write's gate
        int r = tid - w * 85;      // window j * 17 + k
        int j = r / 17;
        int k = r - j * 17;
        float waj = s_wa[j];
        float cl = fminf(fmaxf(waj, -64.0f), (float)memn + 64.0f);
        long long p = (long long)llrintf(cl) - 8 + k;
        s_pg[w][r] = eq_g(s_wa[w], (float)p);
        if (w == 0 && k == 0) d_patch_lo[j] = (int)p;
    }
    __syncthreads();

    // ---- Phase 4b: compose final patched values -> device globals ----
    if (tid < 85) {
        int j = tid / 17;
        int k = tid - j * 17;
        float waj = s_wa[j];
        float cl = fminf(fmaxf(waj, -64.0f), (float)memn + 64.0f);
        long long p = (long long)llrintf(cl) - 8 + k;
        if (p >= 0 && p < (long long)memn) {
            float m = __ldg(&mem[p]);
            #pragma unroll
            for (int i = 0; i < 5; i++) {
                float g = s_pg[i][tid];
                m = m * (1.0f - g) + s_wv[i] * g;
            }
            d_patch_val[tid] = m;
        }
    }
}

// ---------------------------------------------------------------------------
// Fused persistent kernel (R6/R10 layout): block 0 = step; blocks 1..295 each
// copy one contiguous granule-aligned chunk with UNGUARDED MLP-8 batches.
// Source reads are evict-first (.cs); stores default (L2-resident dst).
// ---------------------------------------------------------------------------
__global__ void __launch_bounds__(CPY_THREADS, 2)
fused_kernel(const float* __restrict__ mem,
             const float* __restrict__ pcp,
             const float* __restrict__ spp,
             const float* __restrict__ bpp,
             const float* __restrict__ axp,
             float* __restrict__ out, int memn, int n4, int n4_full, int chunk) {
    int tid = threadIdx.x;

    if (blockIdx.x == 0) {
        step_body(mem, pcp, spp, bpp, axp, out, memn);
    } else {
        const float4* __restrict__ src = (const float4*)mem;
        float4* __restrict__ dst = (float4*)(out + 4);
        int start = (int)(blockIdx.x - 1) * chunk;
        int end   = min(start + chunk, n4_full);
        // Unguarded contiguous MLP-8 batches (granule-aligned start/end).
        for (int base = start + tid; base < end; base += GRAN) {
            float4 v[CPY_V];
            #pragma unroll
            for (int k = 0; k < CPY_V; k++)
                v[k] = __ldcs(&src[base + k * CPY_THREADS]);
            #pragma unroll
            for (int k = 0; k < CPY_V; k++)
                dst[base + k * CPY_THREADS] = v[k];
        }
        // Guarded remainder beyond the last full granule (empty for 16M floats).
        if (blockIdx.x == 1) {
            for (int i = n4_full + tid; i < n4; i += CPY_THREADS)
                dst[i] = __ldg(&src[i]);
        }
    }

    // ---- Last-block patch: runs after every block's work is globally visible
    __shared__ int s_last;
    __threadfence();
    if (tid == 0) {
        int t = atomicAdd(&d_done, 1);
        s_last = (t == (int)gridDim.x - 1);
    }
    __syncthreads();
    if (s_last) {
        __threadfence();  // acquire: see step's patch data + all copies
        if (tid < 85) {
            int j = tid / 17;
            int k = tid - j * 17;
            long long p = (long long)d_patch_lo[j] + k;
            if (p >= 0 && p < (long long)memn)
                out[4 + p] = d_patch_val[tid];
        }
        if (tid == 0) d_done = 0;  // self-reset for graph replay determinism
    }
}

// ---------------------------------------------------------------------------
// Launch
// ---------------------------------------------------------------------------
extern "C" void kernel_launch(void* const* d_in, const int* in_sizes, int n_in,
                              void* d_out, int out_size) {
    int mi = -1;
    for (int i = 0; i < n_in; i++) {
        if (in_sizes[i] > 1) { mi = i; break; }
    }
    const float* mem = (const float*)d_in[mi];
    int memn = in_sizes[mi];

    const float* sc[4];
    int k = 0;
    for (int i = 0; i < n_in && k < 4; i++) {
        if (i == mi) continue;
        sc[k++] = (const float*)d_in[i];
    }

    float* out = (float*)d_out;

    int n4 = memn / 4;                    // 4,194,304 float4
    int n4_full = (n4 / GRAN) * GRAN;     // full granules (== n4 here)
    int n_gran = n4_full / GRAN;
    int g_per = (n_gran + NUM_COPY - 1) / NUM_COPY;
    int chunk = g_per * GRAN;             // granule-aligned contiguous chunk
    fused_kernel<<<NUM_BLOCKS, CPY_THREADS>>>(
        mem, sc[0], sc[1], sc[2], sc[3], out, memn, n4, n4_full, chunk);
}

// round 13
// speedup vs baseline: 1.1075x; 1.1075x over previous
#include <cuda_runtime.h>
#include <cuda_bf16.h>
#include <math.h>

// ---------------------------------------------------------------------------
// Soft-VM single step. eq_gate/silu_threshold with SCALE=20 underflow to exact
// fp32 zero beyond |diff| ~ 5.7, so all soft reads/writes over the 16M-entry
// memory are supported on +/-8 windows. Bulk work = the 128 MB memory copy.
// FINAL SHAPE (best measured, R10): 296 blocks (2/SM), contiguous granule-
// aligned chunks, unguarded MLP-4 batches, evict-first source loads, default
// stores. The copy runs at ~6.7 TB/s aggregate L2 traffic = the B300 LTS
// full-chip cap (path-independent), i.e. at the hardware ceiling. MLP=8 and
// other layouts measured strictly worse (R7, R8, R12).
// ---------------------------------------------------------------------------

#define SCALE_F 20.0f

__device__ __forceinline__ float silu_f(float x) {
    return __fdividef(x, 1.0f + __expf(-x));
}

__device__ __forceinline__ float silu_th(float x) {
    float d = SCALE_F * x;
    return (silu_f(d + 0.5f * SCALE_F) - silu_f(d - 0.5f * SCALE_F)) * (1.0f / SCALE_F);
}

__device__ __forceinline__ float sw_mul(float a, float b) {
    return a * silu_f(b) - a * silu_f(-b);
}

__device__ __forceinline__ float eq_g(float a, float b) {
    float diff = a - b;
    return silu_th(diff + 0.5f) * silu_th(-diff + 0.5f);
}

__device__ __forceinline__ float ge_g(float a, float b) {
    return silu_th(a - b + 0.5f);
}

__device__ __forceinline__ float gt_g(float a, float b) {
    return silu_th(a - b - 0.5f);
}

__device__ __forceinline__ float pulse_f(float x, float c) {
    float d = x - c;
    return sw_mul(silu_th(d + 0.5f), silu_th(-d + 0.5f));
}

__device__ __forceinline__ float warp_sum(float v) {
    #pragma unroll
    for (int o = 16; o > 0; o >>= 1) v += __shfl_down_sync(0xffffffffu, v, o);
    return v;
}

// Opcodes
#define OP_LEA 0
#define OP_IMM 1
#define OP_JMP 2
#define OP_JSR 3
#define OP_BZ  4
#define OP_BNZ 5
#define OP_ENT 6
#define OP_ADJ 7
#define OP_LEV 8
#define OP_LI  9
#define OP_LC  10
#define OP_SI  11
#define OP_SC  12
#define OP_PSH 13
#define OP_SHL 23
#define OP_SHR 24
#define OP_ADD 25
#define OP_SUB 26
#define OP_MUL 27
#define OP_DIV 28
#define OP_MOD 29

// Step -> patch handoff (written by block 0, read by the last block).
__device__ int   d_patch_lo[5];        // window low position per write window
__device__ float d_patch_val[5 * 17];  // composed final values per window slot
__device__ int   d_done = 0;           // last-block counter (self-resetting)

#define CPY_THREADS 512
#define CPY_V       4                       // float4 per thread per batch (MLP=4)
#define GRAN        (CPY_THREADS * CPY_V)   // 2048 float4 = 32 KB granule
#define NUM_BLOCKS  296   // 148 SMs x 2 blocks; block 0 = step, 1..295 = copy
#define NUM_COPY    (NUM_BLOCKS - 1)

// ---------------------------------------------------------------------------
// The step computation (runs entirely inside block 0 of the fused kernel).
// ---------------------------------------------------------------------------
__device__ void step_body(const float* __restrict__ mem,
                          const float* __restrict__ pcp,
                          const float* __restrict__ spp,
                          const float* __restrict__ bpp,
                          const float* __restrict__ axp,
                          float* __restrict__ out, int memn) {
    __shared__ float s_reads[5];   // [inst, stack_top, mem[ax], bp_from_stack, pc_from_stack]
    __shared__ float s_divp[8];
    __shared__ float s_shl_sum, s_shr_sum;
    __shared__ float s_g[30];      // opcode gates
    __shared__ float s_cmp[8];     // extra gates
    __shared__ float s_wa[5], s_wv[5];
    __shared__ float s_pg[5][85];  // patch gates: [write i][window j * 17 + k]

    int tid = threadIdx.x;
    float pc = __ldg(pcp), sp = __ldg(spp), bp = __ldg(bpp), ax = __ldg(axp);

    // ---- Phase 1: 5 windowed soft reads, one warp each, lane-parallel ----
    if (tid < 160) {
        int j = tid >> 5, k = tid & 31;
        float addr = (j == 0) ? pc
                   : (j == 1) ? sp
                   : (j == 2) ? ax
                   : (j == 3) ? bp
                   : (sp + 8.0f);
        float w = 0.0f, wm = 0.0f;
        if (k < 17) {
            float cl = fminf(fmaxf(addr, -64.0f), (float)memn + 64.0f);
            long long p = (long long)llrintf(cl) - 8 + k;
            if (p >= 0 && p < (long long)memn) {
                w  = eq_g(addr, (float)p);
                wm = w * __ldg(&mem[p]);
            }
        }
        w  = warp_sum(w);
        wm = warp_sum(wm);
        if (k == 0) s_reads[j] = wm / (w + 1e-8f);
    }
    __syncthreads();

    float stack_top = s_reads[1];
    float instruction = s_reads[0];
    float imm    = floorf(instruction / 256.0f);
    float opcode = instruction - imm * 256.0f;   // jnp.remainder(inst, 256)
    float ax_safe = ax + eq_g(ax, 0.0f);

    // ---- Phase 2 (parallel): div terms, opcode gates, cmp gates, shifts ----
    if (tid < 256) {
        float q = (float)tid;
        float a = stack_top, b = ax_safe;
        float t1 = a - q * b + 0.5f;
        float th1 = (silu_f(SCALE_F * (t1 + 0.5f)) - silu_f(SCALE_F * (t1 - 0.5f))) * (1.0f / SCALE_F);
        float t2 = a - (q + 1.0f) * b + 0.5f;
        float th2 = (silu_f(SCALE_F * (t2 + 0.5f)) - silu_f(SCALE_F * (t2 - 0.5f))) * (1.0f / SCALE_F);
        float term = warp_sum((th1 - th2) * q);
        if ((tid & 31) == 0) s_divp[tid >> 5] = term;
    } else if (tid < 286) {
        int op = tid - 256;
        s_g[op] = eq_g(opcode, (float)op);
    } else if (tid >= 288 && tid < 320) {
        int l = tid - 288;
        float r = 0.0f;
        if (l == 0) r = eq_g(ax, 0.0f);
        else if (l == 1) r = eq_g(stack_top, ax);
        else if (l == 2) r = gt_g(ax, stack_top);
        else if (l == 3) r = gt_g(stack_top, ax);
        else if (l == 4) r = ge_g(ax, stack_top);
        else if (l == 5) r = ge_g(stack_top, ax);
        else if (l == 6) r = sw_mul(stack_top, ax);
        if (l < 7) s_cmp[l] = r;
    } else if (tid >= 320 && tid < 352) {
        int i = tid - 320;
        float fi = (float)i;
        float p2 = exp2f(fi);
        float pul = pulse_f(ax, fi);
        float shl = sw_mul(stack_top, p2) * pul;
        float shr = floorf(__fdividef(stack_top, p2)) * pul;
        shl = warp_sum(shl);
        shr = warp_sum(shr);
        if (i == 0) { s_shl_sum = shl; s_shr_sum = shr; }
    }
    __syncthreads();

    // ---- Phase 3: thread 0 cheap scalar combine ----
    if (tid == 0) {
        float div_result = 0.0f;
        #pragma unroll
        for (int i = 0; i < 8; i++) div_result += s_divp[i];
        float shl_result = s_shl_sum, shr_result = s_shr_sum;

        float li_result     = s_reads[2];
        float bp_from_stack = s_reads[3];
        float pc_from_stack = s_reads[4];
        float pc_next = pc + 8.0f;

        float eq_ax0    = s_cmp[0];
        float eq_st_ax  = s_cmp[1];
        float mul_st_ax = s_cmp[6];

        float add_r = stack_top + ax;
        float sub_r = stack_top - ax;
        float mul_r = mul_st_ax;
        float mod_r = stack_top - sw_mul(div_result, ax_safe);
        float or_r  = stack_top + ax - mul_st_ax;
        float xor_r = stack_top + ax - 2.0f * mul_st_ax;
        float and_r = mul_st_ax;
        float eq_r  = eq_st_ax;
        float ne_r  = 1.0f - eq_st_ax;
        float lt_r  = s_cmp[2];
        float gt_r  = s_cmp[3];
        float le_r  = s_cmp[4];
        float ge_r  = s_cmp[5];
        float lea_r = bp + imm;

        float gate_sum = s_g[OP_LEA] + s_g[OP_IMM] + s_g[OP_LI] + s_g[OP_LC]
                       + s_g[OP_ADD] + s_g[OP_SUB] + s_g[OP_MUL] + s_g[OP_DIV]
                       + s_g[OP_MOD] + s_g[OP_SHL] + s_g[OP_SHR] + s_g[14]
                       + s_g[15] + s_g[16] + s_g[17] + s_g[18] + s_g[19]
                       + s_g[20] + s_g[21] + s_g[22];

        float new_ax = ax * (1.0f - gate_sum)
                     + lea_r * s_g[OP_LEA] + imm * s_g[OP_IMM]
                     + li_result * s_g[OP_LI] + li_result * s_g[OP_LC]
                     + add_r * s_g[OP_ADD] + sub_r * s_g[OP_SUB] + mul_r * s_g[OP_MUL]
                     + div_result * s_g[OP_DIV] + mod_r * s_g[OP_MOD]
                     + shl_result * s_g[OP_SHL] + shr_result * s_g[OP_SHR]
                     + or_r * s_g[14] + xor_r * s_g[15] + and_r * s_g[16]
                     + eq_r * s_g[17] + ne_r * s_g[18] + lt_r * s_g[19]
                     + gt_r * s_g[20] + le_r * s_g[21] + ge_r * s_g[22];

        float g_psh = s_g[OP_PSH], g_adj = s_g[OP_ADJ];
        float g_ent = s_g[OP_ENT], g_lev = s_g[OP_LEV];

        float pops = s_g[OP_ADD] + s_g[OP_SUB] + s_g[OP_MUL] + s_g[OP_DIV]
                   + s_g[OP_MOD] + s_g[OP_SHL] + s_g[OP_SHR] + s_g[14] + s_g[15]
                   + s_g[16] + s_g[17] + s_g[18] + s_g[19] + s_g[20] + s_g[21]
                   + s_g[22];

        float new_sp = sp * (1.0f - g_psh - g_adj - g_ent - g_lev - pops)
                     + (sp - 8.0f) * g_psh + (sp + imm) * g_adj + (sp - imm) * g_ent
                     + bp * g_lev + (sp + 8.0f) * pops;

        float new_bp = bp * (1.0f - g_ent - g_lev) + sp * g_ent + bp_from_stack * g_lev;

        float g_jmp = s_g[OP_JMP], g_jsr = s_g[OP_JSR];
        float bz_take  = sw_mul(s_g[OP_BZ], eq_ax0);
        float bnz_take = sw_mul(s_g[OP_BNZ], 1.0f - eq_ax0);

        float new_pc = pc_next * (1.0f - g_jmp - g_jsr - bz_take - bnz_take - g_lev)
                     + imm * g_jmp + imm * g_jsr + imm * bz_take + imm * bnz_take
                     + pc_from_stack * g_lev;

        out[0] = rintf(new_pc);   // jnp.round == half-to-even == rintf
        out[1] = rintf(new_sp);
        out[2] = rintf(new_bp);
        out[3] = rintf(new_ax);

        // The 5 sequential soft writes (order matters; composed below)
        s_wa[0] = (sp - 8.0f) * g_psh;      s_wv[0] = ax * g_psh;
        s_wa[1] = (sp - 8.0f) * g_jsr;      s_wv[1] = pc_next * g_jsr;
        s_wa[2] = (sp - 8.0f) * g_ent;      s_wv[2] = bp * g_ent;
        s_wa[3] = stack_top * s_g[OP_SI];   s_wv[3] = ax * s_g[OP_SI];
        s_wa[4] = stack_top * s_g[OP_SC];   s_wv[4] = ax * s_g[OP_SC];
    }
    __syncthreads();

    // ---- Phase 4a: all 5x5x17 patch gates in parallel ----
    if (tid < 425) {
        int w = tid / 85;          // which write's gate
        int r = tid - w * 85;      // window j * 17 + k
        int j = r / 17;
        int k = r - j * 17;
        float waj = s_wa[j];
        float cl = fminf(fmaxf(waj, -64.0f), (float)memn + 64.0f);
        long long p = (long long)llrintf(cl) - 8 + k;
        s_pg[w][r] = eq_g(s_wa[w], (float)p);
        if (w == 0 && k == 0) d_patch_lo[j] = (int)p;
    }
    __syncthreads();

    // ---- Phase 4b: compose final patched values -> device globals ----
    if (tid < 85) {
        int j = tid / 17;
        int k = tid - j * 17;
        float waj = s_wa[j];
        float cl = fminf(fmaxf(waj, -64.0f), (float)memn + 64.0f);
        long long p = (long long)llrintf(cl) - 8 + k;
        if (p >= 0 && p < (long long)memn) {
            float m = __ldg(&mem[p]);
            #pragma unroll
            for (int i = 0; i < 5; i++) {
                float g = s_pg[i][tid];
                m = m * (1.0f - g) + s_wv[i] * g;
            }
            d_patch_val[tid] = m;
        }
    }
}

// ---------------------------------------------------------------------------
// Fused persistent kernel (R10 layout): block 0 = step; blocks 1..295 each
// copy one contiguous granule-aligned chunk with UNGUARDED MLP-4 batches.
// Source reads are evict-first (.cs); stores default (L2-resident dst).
// ---------------------------------------------------------------------------
__global__ void __launch_bounds__(CPY_THREADS, 2)
fused_kernel(const float* __restrict__ mem,
             const float* __restrict__ pcp,
             const float* __restrict__ spp,
             const float* __restrict__ bpp,
             const float* __restrict__ axp,
             float* __restrict__ out, int memn, int n4, int n4_full, int chunk) {
    int tid = threadIdx.x;

    if (blockIdx.x == 0) {
        step_body(mem, pcp, spp, bpp, axp, out, memn);
    } else {
        const float4* __restrict__ src = (const float4*)mem;
        float4* __restrict__ dst = (float4*)(out + 4);
        int start = (int)(blockIdx.x - 1) * chunk;
        int end   = min(start + chunk, n4_full);
        // Unguarded contiguous MLP-4 batches (granule-aligned start/end).
        for (int base = start + tid; base < end; base += GRAN) {
            float4 v[CPY_V];
            #pragma unroll
            for (int k = 0; k < CPY_V; k++)
                v[k] = __ldcs(&src[base + k * CPY_THREADS]);
            #pragma unroll
            for (int k = 0; k < CPY_V; k++)
                dst[base + k * CPY_THREADS] = v[k];
        }
        // Guarded remainder beyond the last full granule (empty for 16M floats).
        if (blockIdx.x == 1) {
            for (int i = n4_full + tid; i < n4; i += CPY_THREADS)
                dst[i] = __ldg(&src[i]);
        }
    }

    // ---- Last-block patch: runs after every block's work is globally visible
    __shared__ int s_last;
    __threadfence();
    if (tid == 0) {
        int t = atomicAdd(&d_done, 1);
        s_last = (t == (int)gridDim.x - 1);
    }
    __syncthreads();
    if (s_last) {
        __threadfence();  // acquire: see step's patch data + all copies
        if (tid < 85) {
            int j = tid / 17;
            int k = tid - j * 17;
            long long p = (long long)d_patch_lo[j] + k;
            if (p >= 0 && p < (long long)memn)
                out[4 + p] = d_patch_val[tid];
        }
        if (tid == 0) d_done = 0;  // self-reset for graph replay determinism
    }
}

// ---------------------------------------------------------------------------
// Launch
// ---------------------------------------------------------------------------
extern "C" void kernel_launch(void* const* d_in, const int* in_sizes, int n_in,
                              void* d_out, int out_size) {
    int mi = -1;
    for (int i = 0; i < n_in; i++) {
        if (in_sizes[i] > 1) { mi = i; break; }
    }
    const float* mem = (const float*)d_in[mi];
    int memn = in_sizes[mi];

    const float* sc[4];
    int k = 0;
    for (int i = 0; i < n_in && k < 4; i++) {
        if (i == mi) continue;
        sc[k++] = (const float*)d_in[i];
    }

    float* out = (float*)d_out;

    int n4 = memn / 4;                    // 4,194,304 float4
    int n4_full = (n4 / GRAN) * GRAN;     // full granules (== n4 here)
    int n_gran = n4_full / GRAN;
    int g_per = (n_gran + NUM_COPY - 1) / NUM_COPY;
    int chunk = g_per * GRAN;             // granule-aligned contiguous chunk
    fused_kernel<<<NUM_BLOCKS, CPY_THREADS>>>(
        mem, sc[0], sc[1], sc[2], sc[3], out, memn, n4, n4_full, chunk);
}